// round 4
// baseline (speedup 1.0000x reference)
#include <cuda_runtime.h>
#include <cuda_bf16.h>
#include <math.h>

#define B 128
#define T 2048
#define H 200
#define G4 800
#define NSTEP 5

// ---- scratch ----
__device__ float g_qproj[B * H];
__device__ float g_hpre [B * G4];
__device__ float g_scores[B * T];
__device__ float g_context[B * H];

__device__ __forceinline__ float tanh_fast(float x) {
    float e = __expf(2.0f * x);
    return 1.0f - __fdividef(2.0f, e + 1.0f);
}
__device__ __forceinline__ float sig_fast(float x) {
    return __fdividef(1.0f, 1.0f + __expf(-x));
}

// ============================================================
// Kernel 1: q_proj and h_pre
// ============================================================
__global__ void k_pre(const float* __restrict__ h0, const float* __restrict__ Wa,
                      const float* __restrict__ ba, const float* __restrict__ Whh,
                      const float* __restrict__ bhh) {
    __shared__ float q[H];
    const int b = blockIdx.x;
    for (int k = threadIdx.x; k < H; k += blockDim.x) q[k] = h0[b * H + k];
    __syncthreads();

    for (int j = threadIdx.x; j < H; j += blockDim.x) {
        const float* w = Wa + j * H;
        float a0 = 0.f, a1 = 0.f;
        #pragma unroll 4
        for (int k = 0; k < H; k += 2) { a0 += w[k] * q[k]; a1 += w[k + 1] * q[k + 1]; }
        g_qproj[b * H + j] = a0 + a1 + ba[j];
    }
    for (int j = threadIdx.x; j < G4; j += blockDim.x) {
        const float* w = Whh + j * H;
        float a0 = 0.f, a1 = 0.f;
        #pragma unroll 4
        for (int k = 0; k < H; k += 2) { a0 += w[k] * q[k]; a1 += w[k + 1] * q[k + 1]; }
        g_hpre[b * G4 + j] = a0 + a1 + bhh[j];
    }
}

// ============================================================
// Kernel 2: score GEMM with packed f32x2 FMA (2x FMA pipe width).
// Tile: 64 t-rows x 200 n-cols, 160 threads.
// Thread tile: 8 m x 10 n (5 f32x2 pairs along n).
//   mg = tid/20 (8 groups of 8 rows)   -> warp lanes mostly share mg => e broadcast
//   ng = tid%20 (20 groups of 10 cols) -> u pairs contiguous in K-transposed sU
// e stored DUPLICATED (v,v) in smem so the pair operand is a single LDS.
// ============================================================
#define TM 64
#define KC 25
#define NTH 160
#define EROW 70      // float2 row stride for sEd (16B-aligned LDS.128)
#define UROW 202     // float row stride for sU (8B-aligned pairs, 2-way fill banks)

#define FMA2(acc, a, bb) asm("fma.rn.f32x2 %0, %1, %2, %0;" : "+l"(acc) : "l"(a), "l"(bb))

__global__ __launch_bounds__(NTH, 2)
void k_scores(const float* __restrict__ enc, const float* __restrict__ Ua,
              const float* __restrict__ bua, const float* __restrict__ Va) {
    __shared__ float2 sEd[KC][EROW];   // duplicated enc tile, [k][m] (14.0 KB)
    __shared__ float  sU [KC][UROW];   // Ua tile transposed,  [k][n] (20.2 KB)
    __shared__ float sQ[H];
    __shared__ float sV[H];
    __shared__ float sS[TM];

    const int b   = blockIdx.y;
    const int t0  = blockIdx.x * TM;
    const int tid = threadIdx.x;

    for (int i = tid; i < H; i += NTH) { sQ[i] = g_qproj[b * H + i] + bua[i]; sV[i] = Va[i]; }
    for (int i = tid; i < TM; i += NTH) sS[i] = 0.f;

    const int mg = tid / 20;
    const int ng = tid % 20;
    const int m0 = mg * 8;
    const int n0 = ng * 10;

    unsigned long long acc[8][5];
    #pragma unroll
    for (int m = 0; m < 8; ++m)
        #pragma unroll
        for (int j = 0; j < 5; ++j) acc[m][j] = 0ull;

    const float* encB = enc + ((long)b * T + t0) * H;

    for (int kb = 0; kb < H; kb += KC) {
        __syncthreads();
        // fill sEd: gmem coalesced (k fastest), value duplicated for f32x2 operand
        for (int i = tid; i < TM * KC; i += NTH) {
            int k = i % KC, m = i / KC;
            float v = encB[m * H + kb + k];
            sEd[k][m] = make_float2(v, v);
        }
        // fill sU transposed: gmem coalesced (k fastest)
        for (int i = tid; i < H * KC; i += NTH) {
            int k = i % KC, n = i / KC;
            sU[k][n] = Ua[n * H + kb + k];
        }
        __syncthreads();

        #pragma unroll 5
        for (int kk = 0; kk < KC; ++kk) {
            unsigned long long e[8], u[5];
            const ulonglong2* ep = (const ulonglong2*)&sEd[kk][m0];
            {   // 4x LDS.128, near-broadcast across warp
                ulonglong2 p0 = ep[0], p1 = ep[1], p2 = ep[2], p3 = ep[3];
                e[0] = p0.x; e[1] = p0.y; e[2] = p1.x; e[3] = p1.y;
                e[4] = p2.x; e[5] = p2.y; e[6] = p3.x; e[7] = p3.y;
            }
            #pragma unroll
            for (int j = 0; j < 5; ++j)
                u[j] = *(const unsigned long long*)&sU[kk][n0 + 2 * j];

            #pragma unroll
            for (int m = 0; m < 8; ++m)
                #pragma unroll
                for (int j = 0; j < 5; ++j)
                    FMA2(acc[m][j], e[m], u[j]);
        }
    }

    // epilogue: tanh + Va-weighted reduce
    float part[8];
    #pragma unroll
    for (int m = 0; m < 8; ++m) part[m] = 0.f;
    #pragma unroll
    for (int j = 0; j < 5; ++j) {
        const int n = n0 + 2 * j;
        const float vq0 = sQ[n],     vv0 = sV[n];
        const float vq1 = sQ[n + 1], vv1 = sV[n + 1];
        #pragma unroll
        for (int m = 0; m < 8; ++m) {
            unsigned long long a = acc[m][j];
            float lo = __uint_as_float((unsigned int)a);
            float hi = __uint_as_float((unsigned int)(a >> 32));
            part[m] += vv0 * tanh_fast(vq0 + lo) + vv1 * tanh_fast(vq1 + hi);
        }
    }
    #pragma unroll
    for (int m = 0; m < 8; ++m) atomicAdd(&sS[m0 + m], part[m]);
    __syncthreads();
    for (int i = tid; i < TM; i += NTH) g_scores[b * T + t0 + i] = sS[i];
}

// ============================================================
// Kernel 3: softmax + context. 800 threads = 4 T-slices x 200 h.
// ============================================================
#define CTXTH 800

__global__ void k_ctx(const float* __restrict__ enc) {
    __shared__ float sW[T];
    __shared__ float sP[4][H];
    __shared__ float red[32];
    const int b = blockIdx.x, tid = threadIdx.x;
    const int lane = tid & 31, wid = tid >> 5;

    float m = -1e30f;
    for (int t = tid; t < T; t += CTXTH) { float s = g_scores[b * T + t]; sW[t] = s; m = fmaxf(m, s); }
    #pragma unroll
    for (int o = 16; o; o >>= 1) m = fmaxf(m, __shfl_xor_sync(0xffffffffu, m, o));
    if (lane == 0) red[wid] = m;
    __syncthreads();
    if (tid < 32) {
        float w = (tid < CTXTH / 32) ? red[tid] : -1e30f;
        #pragma unroll
        for (int o = 16; o; o >>= 1) w = fmaxf(w, __shfl_xor_sync(0xffffffffu, w, o));
        if (tid == 0) red[0] = w;
    }
    __syncthreads();
    m = red[0];
    __syncthreads();

    float sum = 0.f;
    for (int t = tid; t < T; t += CTXTH) { float e = __expf(sW[t] - m); sW[t] = e; sum += e; }
    #pragma unroll
    for (int o = 16; o; o >>= 1) sum += __shfl_xor_sync(0xffffffffu, sum, o);
    if (lane == 0) red[wid] = sum;
    __syncthreads();
    if (tid < 32) {
        float w = (tid < CTXTH / 32) ? red[tid] : 0.f;
        #pragma unroll
        for (int o = 16; o; o >>= 1) w += __shfl_xor_sync(0xffffffffu, w, o);
        if (tid == 0) red[0] = w;
    }
    __syncthreads();
    const float inv = __fdividef(1.0f, red[0]);

    // context partials: slice sl handles t in [sl*512, sl*512+512)
    const int sl = tid / H;        // 0..3
    const int h  = tid - sl * H;   // 0..199
    const float* eB = enc + (long)b * T * H + h;
    float c0 = 0.f, c1 = 0.f, c2 = 0.f, c3 = 0.f;
    const int tbeg = sl * (T / 4), tend = tbeg + (T / 4);
    #pragma unroll 2
    for (int t = tbeg; t < tend; t += 4) {
        c0 += sW[t + 0] * eB[(long)(t + 0) * H];
        c1 += sW[t + 1] * eB[(long)(t + 1) * H];
        c2 += sW[t + 2] * eB[(long)(t + 2) * H];
        c3 += sW[t + 3] * eB[(long)(t + 3) * H];
    }
    sP[sl][h] = c0 + c1 + c2 + c3;
    __syncthreads();
    if (tid < H)
        g_context[b * H + tid] = (sP[0][tid] + sP[1][tid] + sP[2][tid] + sP[3][tid]) * inv;
}

// ============================================================
// Kernel 4: decoder. 800 threads; gates_base 1 row/thread; fast math;
// warp-shuffle final reduction.
// ============================================================
__global__ void k_dec(const float* __restrict__ x, const float* __restrict__ c0in,
                      const float* __restrict__ Wih, const float* __restrict__ bih,
                      const float* __restrict__ W1, const float* __restrict__ b1,
                      const float* __restrict__ W2, const float* __restrict__ b2,
                      const float* __restrict__ W3, const float* __restrict__ b3,
                      float* __restrict__ out) {
    __shared__ float sCtx[H];
    __shared__ float sGB[G4];
    __shared__ float sWx[G4];
    __shared__ float sR[H];
    __shared__ float sO1[100];
    __shared__ float sO2[50];
    __shared__ float sRed[64];
    __shared__ float sY;

    const int b = blockIdx.x, tid = threadIdx.x;
    if (tid < H)  sCtx[tid] = g_context[b * H + tid];
    sWx[tid] = Wih[tid * (H + 1)];     // x-column of W_ih
    __syncthreads();

    // gates_base = context @ W_ih[:,1:].T + b_ih + h_pre  (one row per thread)
    {
        const float* w = Wih + tid * (H + 1) + 1;
        float a0 = bih[tid] + g_hpre[b * G4 + tid], a1 = 0.f;
        #pragma unroll 4
        for (int k = 0; k < H; k += 2) { a0 += w[k] * sCtx[k]; a1 += w[k + 1] * sCtx[k + 1]; }
        sGB[tid] = a0 + a1;
    }
    const float cprev = (tid < H) ? c0in[b * H + tid] : 0.f;
    __syncthreads();

    float xt = x[b];
    for (int s = 0; s < NSTEP; ++s) {
        if (tid < H) {
            const float gi = sGB[tid]         + xt * sWx[tid];
            const float gf = sGB[H + tid]     + xt * sWx[H + tid];
            const float gg = sGB[2 * H + tid] + xt * sWx[2 * H + tid];
            const float go = sGB[3 * H + tid] + xt * sWx[3 * H + tid];
            const float c  = sig_fast(gf) * cprev + sig_fast(gi) * tanh_fast(gg);
            const float h  = sig_fast(go) * tanh_fast(c);
            sR[tid] = fmaxf(h, 0.f);
        }
        __syncthreads();
        if (tid < 100) {
            const float* w = W1 + tid * H;
            float a0 = b1[tid], a1 = 0.f;
            #pragma unroll 4
            for (int k = 0; k < H; k += 2) { a0 += w[k] * sR[k]; a1 += w[k + 1] * sR[k + 1]; }
            sO1[tid] = fmaxf(a0 + a1, 0.f);
        }
        __syncthreads();
        if (tid < 50) {
            const float* w = W2 + tid * 100;
            float a0 = b2[tid], a1 = 0.f;
            #pragma unroll 4
            for (int k = 0; k < 100; k += 2) { a0 += w[k] * sO1[k]; a1 += w[k + 1] * sO1[k + 1]; }
            sO2[tid] = fmaxf(a0 + a1, 0.f);
        }
        __syncthreads();
        if (tid < 64) sRed[tid] = (tid < 50) ? W3[tid] * sO2[tid] : 0.f;
        __syncthreads();
        if (tid < 32) {
            float v = sRed[tid] + sRed[tid + 32];
            #pragma unroll
            for (int o = 16; o; o >>= 1) v += __shfl_xor_sync(0xffffffffu, v, o);
            if (tid == 0) { float y = v + b3[0]; out[b * NSTEP + s] = y; sY = y; }
        }
        __syncthreads();
        xt = sY;
    }
}

// ============================================================
extern "C" void kernel_launch(void* const* d_in, const int* in_sizes, int n_in,
                              void* d_out, int out_size) {
    const float* x   = (const float*)d_in[0];
    const float* h0  = (const float*)d_in[1];
    const float* c0  = (const float*)d_in[2];
    const float* enc = (const float*)d_in[3];
    const float* Wa  = (const float*)d_in[4];
    const float* ba  = (const float*)d_in[5];
    const float* Ua  = (const float*)d_in[6];
    const float* bua = (const float*)d_in[7];
    const float* Va  = (const float*)d_in[8];
    // d_in[9] = bva (softmax-shift-invariant, unused)
    const float* Wih = (const float*)d_in[10];
    const float* Whh = (const float*)d_in[11];
    const float* bih = (const float*)d_in[12];
    const float* bhh = (const float*)d_in[13];
    const float* W1  = (const float*)d_in[14];
    const float* b1  = (const float*)d_in[15];
    const float* W2  = (const float*)d_in[16];
    const float* b2  = (const float*)d_in[17];
    const float* W3  = (const float*)d_in[18];
    const float* b3  = (const float*)d_in[19];
    float* out = (float*)d_out;

    k_pre<<<B, 512>>>(h0, Wa, ba, Whh, bhh);
    k_scores<<<dim3(T / TM, B), NTH>>>(enc, Ua, bua, Va);
    k_ctx<<<B, CTXTH>>>(enc);
    k_dec<<<B, G4>>>(x, c0, Wih, bih, W1, b1, W2, b2, W3, b3, out);
}

// round 7
// speedup vs baseline: 2.1381x; 2.1381x over previous
#include <cuda_runtime.h>
#include <cuda_bf16.h>
#include <math.h>
#include <stdint.h>

#define B 128
#define T 2048
#define H 200
#define G4 800
#define NSTEP 5

// ---- scratch ----
__device__ float g_qproj[B * H];
__device__ float g_hpre [B * G4];
__device__ float g_spart[2][B * T];   // per-z-half score partials (deterministic, no atomics)
__device__ float g_context[B * H];

__device__ __forceinline__ float tanh_fast(float x) {
    float e = __expf(2.0f * x);
    return 1.0f - __fdividef(2.0f, e + 1.0f);
}
__device__ __forceinline__ float sig_fast(float x) {
    return __fdividef(1.0f, 1.0f + __expf(-x));
}
__device__ __forceinline__ uint32_t f2tf32(float x) {
    uint32_t u;
    asm("cvt.rna.tf32.f32 %0, %1;" : "=r"(u) : "f"(x));
    return u;
}
__device__ __forceinline__ void mma_tf32(float* d, const uint32_t* a, const uint32_t* b) {
    asm volatile("mma.sync.aligned.m16n8k8.row.col.f32.tf32.tf32.f32 "
                 "{%0,%1,%2,%3}, {%4,%5,%6,%7}, {%8,%9}, {%0,%1,%2,%3};"
                 : "+f"(d[0]), "+f"(d[1]), "+f"(d[2]), "+f"(d[3])
                 : "r"(a[0]), "r"(a[1]), "r"(a[2]), "r"(a[3]), "r"(b[0]), "r"(b[1]));
}

// ============================================================
// Kernel 1: q_proj and h_pre
// ============================================================
__global__ void k_pre(const float* __restrict__ h0, const float* __restrict__ Wa,
                      const float* __restrict__ ba, const float* __restrict__ Whh,
                      const float* __restrict__ bhh) {
    __shared__ float q[H];
    const int b = blockIdx.x;
    for (int k = threadIdx.x; k < H; k += blockDim.x) q[k] = h0[b * H + k];
    __syncthreads();

    for (int j = threadIdx.x; j < H; j += blockDim.x) {
        const float* w = Wa + j * H;
        float a0 = 0.f, a1 = 0.f;
        #pragma unroll 4
        for (int k = 0; k < H; k += 2) { a0 += w[k] * q[k]; a1 += w[k + 1] * q[k + 1]; }
        g_qproj[b * H + j] = a0 + a1 + ba[j];
    }
    for (int j = threadIdx.x; j < G4; j += blockDim.x) {
        const float* w = Whh + j * H;
        float a0 = 0.f, a1 = 0.f;
        #pragma unroll 4
        for (int k = 0; k < H; k += 2) { a0 += w[k] * q[k]; a1 += w[k + 1] * q[k + 1]; }
        g_hpre[b * G4 + j] = a0 + a1 + bhh[j];
    }
}

// ============================================================
// Kernel 2: score GEMM via mma.sync tf32 (sm_80+ ISA, no 'a'-suffix needed).
// Grid (T/128, B, 2). Block tile: 128 t-rows x 112 n-cols, full K (pad 224).
// 8 warps = 4(m) x 2(n); warp tile 32 rows x 56 cols = 2x7 m16n8k8 tiles.
// Smem stride 36 => fragment LDS bank = 4q+c : conflict-free.
// Epilogue: tanh + Va-reduce in registers -> row partials -> g_spart[z].
// ============================================================
#define NB 112
#define KCH 32
#define NKCH 7

__global__ __launch_bounds__(256, 2)
void k_scores_mma(const float* __restrict__ enc, const float* __restrict__ Ua,
                  const float* __restrict__ bua, const float* __restrict__ Va) {
    __shared__ uint32_t sA[128][36];   // enc tile (tf32 bits), [m][k]
    __shared__ uint32_t sB[NB][36];    // Ua tile  (tf32 bits), [n][k]
    __shared__ float sQ[NB];
    __shared__ float sV[NB];
    __shared__ float sRow[128];

    const int tid  = threadIdx.x;
    const int wid  = tid >> 5, lane = tid & 31;
    const int b    = blockIdx.y;
    const int t0   = blockIdx.x * 128;
    const int zi   = blockIdx.z;
    const int n0g  = zi * NB;

    const int mw = wid & 3;
    const int nw = wid >> 2;
    const int rowbase = mw * 32;
    const int nbase   = nw * 56;
    const int q = lane >> 2;
    const int c = lane & 3;

    for (int i = tid; i < NB; i += 256) {
        const int col = n0g + i;
        sQ[i] = (col < H) ? g_qproj[b * H + col] + bua[col] : 0.f;
        sV[i] = (col < H) ? Va[col] : 0.f;
    }
    if (tid < 128) sRow[tid] = 0.f;

    float acc[2][7][4];
    #pragma unroll
    for (int mt = 0; mt < 2; ++mt)
        #pragma unroll
        for (int nt = 0; nt < 7; ++nt)
            #pragma unroll
            for (int j = 0; j < 4; ++j) acc[mt][nt][j] = 0.f;

    const float* encB = enc + ((long)b * T + t0) * H;

    for (int kc = 0; kc < NKCH; ++kc) {
        const int k0 = kc * KCH;
        __syncthreads();
        for (int i = tid; i < 128 * 8; i += 256) {
            const int row = i >> 3, g = i & 7;
            const int gk = k0 + g * 4;
            float4 v = make_float4(0.f, 0.f, 0.f, 0.f);
            if (gk + 3 < H) v = *(const float4*)(encB + (long)row * H + gk);
            uint4 u = make_uint4(f2tf32(v.x), f2tf32(v.y), f2tf32(v.z), f2tf32(v.w));
            *(uint4*)&sA[row][g * 4] = u;
        }
        for (int i = tid; i < NB * 8; i += 256) {
            const int row = i >> 3, g = i & 7;
            const int gk = k0 + g * 4;
            const int ng = n0g + row;
            float4 v = make_float4(0.f, 0.f, 0.f, 0.f);
            if (ng < H && gk + 3 < H) v = *(const float4*)(Ua + (long)ng * H + gk);
            uint4 u = make_uint4(f2tf32(v.x), f2tf32(v.y), f2tf32(v.z), f2tf32(v.w));
            *(uint4*)&sB[row][g * 4] = u;
        }
        __syncthreads();

        #pragma unroll
        for (int ks = 0; ks < 4; ++ks) {
            const int kk = ks * 8;
            uint32_t afr[2][4];
            #pragma unroll
            for (int mt = 0; mt < 2; ++mt) {
                const int R = rowbase + mt * 16 + q;
                afr[mt][0] = sA[R][kk + c];
                afr[mt][1] = sA[R + 8][kk + c];
                afr[mt][2] = sA[R][kk + c + 4];
                afr[mt][3] = sA[R + 8][kk + c + 4];
            }
            uint32_t bfr[7][2];
            #pragma unroll
            for (int nt = 0; nt < 7; ++nt) {
                const int N = nbase + nt * 8 + q;
                bfr[nt][0] = sB[N][kk + c];
                bfr[nt][1] = sB[N][kk + c + 4];
            }
            #pragma unroll
            for (int mt = 0; mt < 2; ++mt)
                #pragma unroll
                for (int nt = 0; nt < 7; ++nt)
                    mma_tf32(acc[mt][nt], afr[mt], bfr[nt]);
        }
    }

    // ---- epilogue: tanh + Va reduce ----
    float pLo[2], pHi[2];
    #pragma unroll
    for (int mt = 0; mt < 2; ++mt) { pLo[mt] = 0.f; pHi[mt] = 0.f; }
    #pragma unroll
    for (int nt = 0; nt < 7; ++nt) {
        const int col0 = nbase + nt * 8 + c * 2;
        const float v0 = sV[col0],     q0 = sQ[col0];
        const float v1 = sV[col0 + 1], q1 = sQ[col0 + 1];
        #pragma unroll
        for (int mt = 0; mt < 2; ++mt) {
            pLo[mt] += v0 * tanh_fast(q0 + acc[mt][nt][0]) + v1 * tanh_fast(q1 + acc[mt][nt][1]);
            pHi[mt] += v0 * tanh_fast(q0 + acc[mt][nt][2]) + v1 * tanh_fast(q1 + acc[mt][nt][3]);
        }
    }
    // reduce across the 4 lanes sharing each row (full warps execute uniformly)
    #pragma unroll
    for (int mt = 0; mt < 2; ++mt) {
        #pragma unroll
        for (int o = 1; o <= 2; o <<= 1) {
            pLo[mt] += __shfl_xor_sync(0xffffffffu, pLo[mt], o);
            pHi[mt] += __shfl_xor_sync(0xffffffffu, pHi[mt], o);
        }
        if (c == 0) {
            const int R = rowbase + mt * 16 + q;
            atomicAdd(&sRow[R], pLo[mt]);       // shared atomics: deterministic value (fp add assoc within 2 n-warps only — reduced below)
            atomicAdd(&sRow[R + 8], pHi[mt]);
        }
    }
    __syncthreads();
    if (tid < 128) g_spart[zi][b * T + t0 + tid] = sRow[tid];
}

// ============================================================
// Kernel 3: softmax + context. 800 threads = 4 T-slices x 200 h.
// Scores assembled from the two z-half partials.
// ============================================================
#define CTXTH 800

__global__ void k_ctx(const float* __restrict__ enc) {
    __shared__ float sW[T];
    __shared__ float sP[4][H];
    __shared__ float red[32];
    const int b = blockIdx.x, tid = threadIdx.x;
    const int lane = tid & 31, wid = tid >> 5;

    float m = -1e30f;
    for (int t = tid; t < T; t += CTXTH) {
        float s = g_spart[0][b * T + t] + g_spart[1][b * T + t];
        sW[t] = s; m = fmaxf(m, s);
    }
    #pragma unroll
    for (int o = 16; o; o >>= 1) m = fmaxf(m, __shfl_xor_sync(0xffffffffu, m, o));
    if (lane == 0) red[wid] = m;
    __syncthreads();
    if (tid < 32) {
        float w = (tid < CTXTH / 32) ? red[tid] : -1e30f;
        #pragma unroll
        for (int o = 16; o; o >>= 1) w = fmaxf(w, __shfl_xor_sync(0xffffffffu, w, o));
        if (tid == 0) red[0] = w;
    }
    __syncthreads();
    m = red[0];
    __syncthreads();

    float sum = 0.f;
    for (int t = tid; t < T; t += CTXTH) { float e = __expf(sW[t] - m); sW[t] = e; sum += e; }
    #pragma unroll
    for (int o = 16; o; o >>= 1) sum += __shfl_xor_sync(0xffffffffu, sum, o);
    if (lane == 0) red[wid] = sum;
    __syncthreads();
    if (tid < 32) {
        float w = (tid < CTXTH / 32) ? red[tid] : 0.f;
        #pragma unroll
        for (int o = 16; o; o >>= 1) w += __shfl_xor_sync(0xffffffffu, w, o);
        if (tid == 0) red[0] = w;
    }
    __syncthreads();
    const float inv = __fdividef(1.0f, red[0]);

    const int sl = tid / H;
    const int h  = tid - sl * H;
    const float* eB = enc + (long)b * T * H + h;
    float c0 = 0.f, c1 = 0.f, c2 = 0.f, c3 = 0.f;
    const int tbeg = sl * (T / 4), tend = tbeg + (T / 4);
    #pragma unroll 2
    for (int t = tbeg; t < tend; t += 4) {
        c0 += sW[t + 0] * eB[(long)(t + 0) * H];
        c1 += sW[t + 1] * eB[(long)(t + 1) * H];
        c2 += sW[t + 2] * eB[(long)(t + 2) * H];
        c3 += sW[t + 3] * eB[(long)(t + 3) * H];
    }
    sP[sl][h] = c0 + c1 + c2 + c3;
    __syncthreads();
    if (tid < H)
        g_context[b * H + tid] = (sP[0][tid] + sP[1][tid] + sP[2][tid] + sP[3][tid]) * inv;
}

// ============================================================
// Kernel 4: decoder. 800 threads; split-K GEMVs with PER-GROUP shuffle
// masks (0xF << group-base-lane) — no partial-warp full-mask shuffles.
// ============================================================
__global__ void k_dec(const float* __restrict__ x, const float* __restrict__ c0in,
                      const float* __restrict__ Wih, const float* __restrict__ bih,
                      const float* __restrict__ W1, const float* __restrict__ b1,
                      const float* __restrict__ W2, const float* __restrict__ b2,
                      const float* __restrict__ W3, const float* __restrict__ b3,
                      float* __restrict__ out) {
    __shared__ float sCtx[H];
    __shared__ float sGB[G4];
    __shared__ float sWx[G4];
    __shared__ float sR[H];
    __shared__ float sO1[100];
    __shared__ float sO2[50];
    __shared__ float sRed[64];
    __shared__ float sY;

    const int b = blockIdx.x, tid = threadIdx.x;
    const int lane = tid & 31;
    const unsigned gmask = 0xFu << (lane & 28);   // the 4-lane reduction group

    if (tid < H)  sCtx[tid] = g_context[b * H + tid];
    sWx[tid] = Wih[tid * (H + 1)];
    __syncthreads();

    {
        const float* w = Wih + tid * (H + 1) + 1;
        float a0 = bih[tid] + g_hpre[b * G4 + tid], a1 = 0.f;
        #pragma unroll 4
        for (int k = 0; k < H; k += 2) { a0 += w[k] * sCtx[k]; a1 += w[k + 1] * sCtx[k + 1]; }
        sGB[tid] = a0 + a1;
    }
    const float cprev = (tid < H) ? c0in[b * H + tid] : 0.f;
    __syncthreads();

    float xt = x[b];
    const int j4 = tid >> 2, q4 = tid & 3;
    for (int s = 0; s < NSTEP; ++s) {
        if (tid < H) {
            const float gi = sGB[tid]         + xt * sWx[tid];
            const float gf = sGB[H + tid]     + xt * sWx[H + tid];
            const float gg = sGB[2 * H + tid] + xt * sWx[2 * H + tid];
            const float go = sGB[3 * H + tid] + xt * sWx[3 * H + tid];
            const float c  = sig_fast(gf) * cprev + sig_fast(gi) * tanh_fast(gg);
            const float h  = sig_fast(go) * tanh_fast(c);
            sR[tid] = fmaxf(h, 0.f);
        }
        __syncthreads();
        // W1: 100 outputs x 4 threads (tids 0..399; every 4-lane group intact)
        if (tid < 400) {
            const float* w = W1 + j4 * H + q4 * 50;
            const float* r = sR + q4 * 50;
            float a0 = 0.f, a1 = 0.f;
            #pragma unroll 5
            for (int k = 0; k < 50; k += 2) { a0 += w[k] * r[k]; a1 += w[k + 1] * r[k + 1]; }
            float v = a0 + a1;
            v += __shfl_xor_sync(gmask, v, 1);
            v += __shfl_xor_sync(gmask, v, 2);
            if (q4 == 0) sO1[j4] = fmaxf(v + b1[j4], 0.f);
        }
        __syncthreads();
        // W2: 50 outputs x 4 threads (tids 0..199)
        if (tid < 200) {
            const float* w = W2 + j4 * 100 + q4 * 25;
            const float* r = sO1 + q4 * 25;
            float a0 = 0.f;
            #pragma unroll 5
            for (int k = 0; k < 25; ++k) a0 += w[k] * r[k];
            float v = a0;
            v += __shfl_xor_sync(gmask, v, 1);
            v += __shfl_xor_sync(gmask, v, 2);
            if (q4 == 0) sO2[j4] = fmaxf(v + b2[j4], 0.f);
        }
        __syncthreads();
        if (tid < 64) sRed[tid] = (tid < 50) ? W3[tid] * sO2[tid] : 0.f;
        __syncthreads();
        if (tid < 32) {
            float v = sRed[tid] + sRed[tid + 32];
            #pragma unroll
            for (int o = 16; o; o >>= 1) v += __shfl_xor_sync(0xffffffffu, v, o);
            if (tid == 0) { float y = v + b3[0]; out[b * NSTEP + s] = y; sY = y; }
        }
        __syncthreads();
        xt = sY;
    }
}

// ============================================================
extern "C" void kernel_launch(void* const* d_in, const int* in_sizes, int n_in,
                              void* d_out, int out_size) {
    const float* x   = (const float*)d_in[0];
    const float* h0  = (const float*)d_in[1];
    const float* c0  = (const float*)d_in[2];
    const float* enc = (const float*)d_in[3];
    const float* Wa  = (const float*)d_in[4];
    const float* ba  = (const float*)d_in[5];
    const float* Ua  = (const float*)d_in[6];
    const float* bua = (const float*)d_in[7];
    const float* Va  = (const float*)d_in[8];
    // d_in[9] = bva (softmax-shift-invariant, unused)
    const float* Wih = (const float*)d_in[10];
    const float* Whh = (const float*)d_in[11];
    const float* bih = (const float*)d_in[12];
    const float* bhh = (const float*)d_in[13];
    const float* W1  = (const float*)d_in[14];
    const float* b1  = (const float*)d_in[15];
    const float* W2  = (const float*)d_in[16];
    const float* b2  = (const float*)d_in[17];
    const float* W3  = (const float*)d_in[18];
    const float* b3  = (const float*)d_in[19];
    float* out = (float*)d_out;

    k_pre<<<B, 512>>>(h0, Wa, ba, Whh, bhh);
    k_scores_mma<<<dim3(T / 128, B, 2), 256>>>(enc, Ua, bua, Va);
    k_ctx<<<B, CTXTH>>>(enc);
    k_dec<<<B, G4>>>(x, c0, Wih, bih, W1, b1, W2, b2, W3, b3, out);
}

// round 8
// speedup vs baseline: 3.4779x; 1.6266x over previous
#include <cuda_runtime.h>
#include <cuda_bf16.h>
#include <math.h>
#include <stdint.h>

#define B 128
#define T 2048
#define H 200
#define G4 800
#define NSTEP 5

// ---- scratch ----
__device__ float g_qproj[B * H];
__device__ float g_hpre [B * G4];
__device__ float g_spart[2][B * T];   // per-z-half score partials
__device__ float g_context[B * H];

__device__ __forceinline__ float tanh_fast(float x) {
    float e = __expf(2.0f * x);
    return 1.0f - __fdividef(2.0f, e + 1.0f);
}
__device__ __forceinline__ float sig_fast(float x) {
    return __fdividef(1.0f, 1.0f + __expf(-x));
}
__device__ __forceinline__ uint32_t smem_u32(const void* p) {
    uint32_t a;
    asm("{ .reg .u64 t; cvta.to.shared.u64 t, %1; cvt.u32.u64 %0, t; }" : "=r"(a) : "l"(p));
    return a;
}
__device__ __forceinline__ void cp_async16(uint32_t dst, const void* src, uint32_t src_sz) {
    asm volatile("cp.async.cg.shared.global [%0], [%1], 16, %2;"
                 :: "r"(dst), "l"(src), "r"(src_sz) : "memory");
}
__device__ __forceinline__ void mma_tf32(float* d, const uint32_t* a, const uint32_t* b) {
    asm volatile("mma.sync.aligned.m16n8k8.row.col.f32.tf32.tf32.f32 "
                 "{%0,%1,%2,%3}, {%4,%5,%6,%7}, {%8,%9}, {%0,%1,%2,%3};"
                 : "+f"(d[0]), "+f"(d[1]), "+f"(d[2]), "+f"(d[3])
                 : "r"(a[0]), "r"(a[1]), "r"(a[2]), "r"(a[3]), "r"(b[0]), "r"(b[1]));
}

// ============================================================
// Kernel 1: q_proj and h_pre
// ============================================================
__global__ void k_pre(const float* __restrict__ h0, const float* __restrict__ Wa,
                      const float* __restrict__ ba, const float* __restrict__ Whh,
                      const float* __restrict__ bhh) {
    __shared__ float q[H];
    const int b = blockIdx.x;
    for (int k = threadIdx.x; k < H; k += blockDim.x) q[k] = h0[b * H + k];
    __syncthreads();

    for (int j = threadIdx.x; j < H; j += blockDim.x) {
        const float* w = Wa + j * H;
        float a0 = 0.f, a1 = 0.f;
        #pragma unroll 4
        for (int k = 0; k < H; k += 2) { a0 += w[k] * q[k]; a1 += w[k + 1] * q[k + 1]; }
        g_qproj[b * H + j] = a0 + a1 + ba[j];
    }
    for (int j = threadIdx.x; j < G4; j += blockDim.x) {
        const float* w = Whh + j * H;
        float a0 = 0.f, a1 = 0.f;
        #pragma unroll 4
        for (int k = 0; k < H; k += 2) { a0 += w[k] * q[k]; a1 += w[k + 1] * q[k + 1]; }
        g_hpre[b * G4 + j] = a0 + a1 + bhh[j];
    }
}

// ============================================================
// Kernel 2: score GEMM via mma.sync tf32 + cp.async double-buffer.
// Grid (T/128, B, 2). Block tile: 128 t x 112 n, K chunks of 16 (13 chunks, pad 208).
// Raw fp32 bits fed to tf32 mma (HW reads top 19 bits).
// Smem rows stride 20 floats (80B: 16B-aligned, conflict-free fragments).
// ============================================================
#define NB 112
#define KCH 16
#define NKCH 13      // 13*16 = 208 >= 200
#define SSTR 20      // row stride in floats

__global__ __launch_bounds__(256, 2)
void k_scores_mma(const float* __restrict__ enc, const float* __restrict__ Ua,
                  const float* __restrict__ bua, const float* __restrict__ Va) {
    __shared__ __align__(16) uint32_t sA2[2][128][SSTR];  // 20.0 KB
    __shared__ __align__(16) uint32_t sB2[2][NB][SSTR];   // 17.5 KB
    __shared__ float sQ[NB];
    __shared__ float sV[NB];
    __shared__ float sRow[128];

    const int tid  = threadIdx.x;
    const int wid  = tid >> 5, lane = tid & 31;
    const int b    = blockIdx.y;
    const int t0   = blockIdx.x * 128;
    const int zi   = blockIdx.z;
    const int n0g  = zi * NB;

    const int mw = wid & 3;
    const int nw = wid >> 2;
    const int rowbase = mw * 32;
    const int nbase   = nw * 56;
    const int q = lane >> 2;
    const int c = lane & 3;

    for (int i = tid; i < NB; i += 256) {
        const int col = n0g + i;
        sQ[i] = (col < H) ? g_qproj[b * H + col] + bua[col] : 0.f;
        sV[i] = (col < H) ? Va[col] : 0.f;
    }
    if (tid < 128) sRow[tid] = 0.f;

    float acc[2][7][4];
    #pragma unroll
    for (int mt = 0; mt < 2; ++mt)
        #pragma unroll
        for (int nt = 0; nt < 7; ++nt)
            #pragma unroll
            for (int j = 0; j < 4; ++j) acc[mt][nt][j] = 0.f;

    const float* encB = enc + ((long)b * T + t0) * H;
    const uint32_t aBase = smem_u32(&sA2[0][0][0]);
    const uint32_t bBase = smem_u32(&sB2[0][0][0]);

    // --- async fill of one stage ---
    auto fill = [&](int kc, int st) {
        const int k0 = kc * KCH;
        const uint32_t aSt = aBase + (uint32_t)st * 128 * SSTR * 4;
        const uint32_t bSt = bBase + (uint32_t)st * NB * SSTR * 4;
        // A: 128 rows x 4 groups of 16B
        for (int i = tid; i < 128 * 4; i += 256) {
            const int row = i >> 2, g = i & 3;
            const int gk = k0 + g * 4;
            const bool ok = (gk + 4 <= H);
            const float* src = ok ? (encB + (long)row * H + gk) : encB;
            cp_async16(aSt + (uint32_t)(row * SSTR + g * 4) * 4, src, ok ? 16u : 0u);
        }
        // B: 112 rows x 4 groups
        for (int i = tid; i < NB * 4; i += 256) {
            const int row = i >> 2, g = i & 3;
            const int ng = n0g + row;
            const int gk = k0 + g * 4;
            const bool ok = (ng < H) && (gk + 4 <= H);
            const float* src = ok ? (Ua + (long)ng * H + gk) : Ua;
            cp_async16(bSt + (uint32_t)(row * SSTR + g * 4) * 4, src, ok ? 16u : 0u);
        }
        asm volatile("cp.async.commit_group;" ::: "memory");
    };

    fill(0, 0);

    for (int kc = 0; kc < NKCH; ++kc) {
        const int st = kc & 1;
        if (kc + 1 < NKCH) {
            fill(kc + 1, st ^ 1);
            asm volatile("cp.async.wait_group 1;" ::: "memory");
        } else {
            asm volatile("cp.async.wait_group 0;" ::: "memory");
        }
        __syncthreads();

        #pragma unroll
        for (int ks = 0; ks < 2; ++ks) {
            const int kk = ks * 8;
            uint32_t afr[2][4];
            #pragma unroll
            for (int mt = 0; mt < 2; ++mt) {
                const int R = rowbase + mt * 16 + q;
                afr[mt][0] = sA2[st][R][kk + c];
                afr[mt][1] = sA2[st][R + 8][kk + c];
                afr[mt][2] = sA2[st][R][kk + c + 4];
                afr[mt][3] = sA2[st][R + 8][kk + c + 4];
            }
            uint32_t bfr[7][2];
            #pragma unroll
            for (int nt = 0; nt < 7; ++nt) {
                const int N = nbase + nt * 8 + q;
                bfr[nt][0] = sB2[st][N][kk + c];
                bfr[nt][1] = sB2[st][N][kk + c + 4];
            }
            #pragma unroll
            for (int mt = 0; mt < 2; ++mt)
                #pragma unroll
                for (int nt = 0; nt < 7; ++nt)
                    mma_tf32(acc[mt][nt], afr[mt], bfr[nt]);
        }
        __syncthreads();   // protect stage st before it is refilled at kc+2
    }

    // ---- epilogue: tanh + Va reduce ----
    float pLo[2], pHi[2];
    #pragma unroll
    for (int mt = 0; mt < 2; ++mt) { pLo[mt] = 0.f; pHi[mt] = 0.f; }
    #pragma unroll
    for (int nt = 0; nt < 7; ++nt) {
        const int col0 = nbase + nt * 8 + c * 2;
        const float v0 = sV[col0],     q0 = sQ[col0];
        const float v1 = sV[col0 + 1], q1 = sQ[col0 + 1];
        #pragma unroll
        for (int mt = 0; mt < 2; ++mt) {
            pLo[mt] += v0 * tanh_fast(q0 + acc[mt][nt][0]) + v1 * tanh_fast(q1 + acc[mt][nt][1]);
            pHi[mt] += v0 * tanh_fast(q0 + acc[mt][nt][2]) + v1 * tanh_fast(q1 + acc[mt][nt][3]);
        }
    }
    #pragma unroll
    for (int mt = 0; mt < 2; ++mt) {
        #pragma unroll
        for (int o = 1; o <= 2; o <<= 1) {
            pLo[mt] += __shfl_xor_sync(0xffffffffu, pLo[mt], o);
            pHi[mt] += __shfl_xor_sync(0xffffffffu, pHi[mt], o);
        }
        if (c == 0) {
            const int R = rowbase + mt * 16 + q;
            atomicAdd(&sRow[R], pLo[mt]);
            atomicAdd(&sRow[R + 8], pHi[mt]);
        }
    }
    __syncthreads();
    if (tid < 128) g_spart[zi][b * T + t0 + tid] = sRow[tid];
}

// ============================================================
// Kernel 3: softmax + context. 800 threads = 4 T-slices x 200 h.
// ============================================================
#define CTXTH 800

__global__ void k_ctx(const float* __restrict__ enc) {
    __shared__ float sW[T];
    __shared__ float sP[4][H];
    __shared__ float red[32];
    const int b = blockIdx.x, tid = threadIdx.x;
    const int lane = tid & 31, wid = tid >> 5;

    float m = -1e30f;
    for (int t = tid; t < T; t += CTXTH) {
        float s = g_spart[0][b * T + t] + g_spart[1][b * T + t];
        sW[t] = s; m = fmaxf(m, s);
    }
    #pragma unroll
    for (int o = 16; o; o >>= 1) m = fmaxf(m, __shfl_xor_sync(0xffffffffu, m, o));
    if (lane == 0) red[wid] = m;
    __syncthreads();
    if (tid < 32) {
        float w = (tid < CTXTH / 32) ? red[tid] : -1e30f;
        #pragma unroll
        for (int o = 16; o; o >>= 1) w = fmaxf(w, __shfl_xor_sync(0xffffffffu, w, o));
        if (tid == 0) red[0] = w;
    }
    __syncthreads();
    m = red[0];
    __syncthreads();

    float sum = 0.f;
    for (int t = tid; t < T; t += CTXTH) { float e = __expf(sW[t] - m); sW[t] = e; sum += e; }
    #pragma unroll
    for (int o = 16; o; o >>= 1) sum += __shfl_xor_sync(0xffffffffu, sum, o);
    if (lane == 0) red[wid] = sum;
    __syncthreads();
    if (tid < 32) {
        float w = (tid < CTXTH / 32) ? red[tid] : 0.f;
        #pragma unroll
        for (int o = 16; o; o >>= 1) w += __shfl_xor_sync(0xffffffffu, w, o);
        if (tid == 0) red[0] = w;
    }
    __syncthreads();
    const float inv = __fdividef(1.0f, red[0]);

    const int sl = tid / H;
    const int h  = tid - sl * H;
    const float* eB = enc + (long)b * T * H + h;
    float c0 = 0.f, c1 = 0.f, c2 = 0.f, c3 = 0.f;
    const int tbeg = sl * (T / 4), tend = tbeg + (T / 4);
    #pragma unroll 2
    for (int t = tbeg; t < tend; t += 4) {
        c0 += sW[t + 0] * eB[(long)(t + 0) * H];
        c1 += sW[t + 1] * eB[(long)(t + 1) * H];
        c2 += sW[t + 2] * eB[(long)(t + 2) * H];
        c3 += sW[t + 3] * eB[(long)(t + 3) * H];
    }
    sP[sl][h] = c0 + c1 + c2 + c3;
    __syncthreads();
    if (tid < H)
        g_context[b * H + tid] = (sP[0][tid] + sP[1][tid] + sP[2][tid] + sP[3][tid]) * inv;
}

// ============================================================
// Kernel 4: decoder. 800 threads. W1 hoisted to registers (8 thr/output,
// 25 w each), W2/W3/biases to smem ONCE — the 5 steps touch only
// smem/registers. Per-group shuffle masks (no partial-warp full-mask).
// ============================================================
__global__ void k_dec(const float* __restrict__ x, const float* __restrict__ c0in,
                      const float* __restrict__ Wih, const float* __restrict__ bih,
                      const float* __restrict__ W1, const float* __restrict__ b1,
                      const float* __restrict__ W2, const float* __restrict__ b2,
                      const float* __restrict__ W3, const float* __restrict__ b3,
                      float* __restrict__ out) {
    __shared__ float sCtx[H];
    __shared__ float sGB[G4];
    __shared__ float sWx[G4];
    __shared__ float sR[H];
    __shared__ float sO1[100];
    __shared__ float sO2[52];
    __shared__ float sRed[64];
    __shared__ float sY;
    __shared__ float sW2[5000];
    __shared__ float sW3[52];
    __shared__ float sB1[100];
    __shared__ float sB2c[52];

    const int b = blockIdx.x, tid = threadIdx.x;
    const int lane = tid & 31;
    const unsigned m8  = 0xFFu   << (lane & 24);
    const unsigned m16 = 0xFFFFu << (lane & 16);

    // one-time loads
    for (int i = tid; i < 5000; i += G4) sW2[i] = W2[i];
    if (tid < 50)  sW3[tid] = W3[tid];
    if (tid < 100) sB1[tid] = b1[tid];
    if (tid < 50)  sB2c[tid] = b2[tid];
    if (tid < H)   sCtx[tid] = g_context[b * H + tid];
    sWx[tid] = Wih[tid * (H + 1)];

    const int j8 = tid >> 3, q8 = tid & 7;      // 100 outputs x 8 threads
    float w1r[25];
    {
        const float* w1p = W1 + j8 * H + q8 * 25;
        #pragma unroll
        for (int k = 0; k < 25; ++k) w1r[k] = w1p[k];
    }
    __syncthreads();

    // gates_base = context @ W_ih[:,1:].T + b_ih + h_pre
    {
        const float* w = Wih + tid * (H + 1) + 1;
        float a0 = bih[tid] + g_hpre[b * G4 + tid], a1 = 0.f;
        #pragma unroll 4
        for (int k = 0; k < H; k += 2) { a0 += w[k] * sCtx[k]; a1 += w[k + 1] * sCtx[k + 1]; }
        sGB[tid] = a0 + a1;
    }
    const float cprev = (tid < H) ? c0in[b * H + tid] : 0.f;
    __syncthreads();

    float xt = x[b];
    const int j16 = tid >> 4, q16 = tid & 15;   // 50 outputs x 16 threads
    for (int s = 0; s < NSTEP; ++s) {
        if (tid < H) {
            const float gi = sGB[tid]         + xt * sWx[tid];
            const float gf = sGB[H + tid]     + xt * sWx[H + tid];
            const float gg = sGB[2 * H + tid] + xt * sWx[2 * H + tid];
            const float go = sGB[3 * H + tid] + xt * sWx[3 * H + tid];
            const float c  = sig_fast(gf) * cprev + sig_fast(gi) * tanh_fast(gg);
            const float h  = sig_fast(go) * tanh_fast(c);
            sR[tid] = fmaxf(h, 0.f);
        }
        __syncthreads();
        // W1 from registers: all 800 threads active, 8-lane groups
        {
            const float* r = sR + q8 * 25;
            float v = 0.f;
            #pragma unroll
            for (int k = 0; k < 25; ++k) v += w1r[k] * r[k];
            v += __shfl_xor_sync(m8, v, 1);
            v += __shfl_xor_sync(m8, v, 2);
            v += __shfl_xor_sync(m8, v, 4);
            if (q8 == 0) sO1[j8] = fmaxf(v + sB1[j8], 0.f);
        }
        __syncthreads();
        // W2 from smem: all 800 threads, 16-lane groups (7 k each, guarded)
        {
            const float* w = sW2 + j16 * 100;
            float v = 0.f;
            #pragma unroll
            for (int kk = 0; kk < 7; ++kk) {
                const int k = q16 * 7 + kk;
                if (k < 100) v += w[k] * sO1[k];
            }
            v += __shfl_xor_sync(m16, v, 1);
            v += __shfl_xor_sync(m16, v, 2);
            v += __shfl_xor_sync(m16, v, 4);
            v += __shfl_xor_sync(m16, v, 8);
            if (q16 == 0) sO2[j16] = fmaxf(v + sB2c[j16], 0.f);
        }
        __syncthreads();
        if (tid < 64) sRed[tid] = (tid < 50) ? sW3[tid] * sO2[tid] : 0.f;
        __syncthreads();
        if (tid < 32) {
            float v = sRed[tid] + sRed[tid + 32];
            #pragma unroll
            for (int o = 16; o; o >>= 1) v += __shfl_xor_sync(0xffffffffu, v, o);
            if (tid == 0) { float y = v + b3[0]; out[b * NSTEP + s] = y; sY = y; }
        }
        __syncthreads();
        xt = sY;
    }
}

// ============================================================
extern "C" void kernel_launch(void* const* d_in, const int* in_sizes, int n_in,
                              void* d_out, int out_size) {
    const float* x   = (const float*)d_in[0];
    const float* h0  = (const float*)d_in[1];
    const float* c0  = (const float*)d_in[2];
    const float* enc = (const float*)d_in[3];
    const float* Wa  = (const float*)d_in[4];
    const float* ba  = (const float*)d_in[5];
    const float* Ua  = (const float*)d_in[6];
    const float* bua = (const float*)d_in[7];
    const float* Va  = (const float*)d_in[8];
    // d_in[9] = bva (softmax-shift-invariant, unused)
    const float* Wih = (const float*)d_in[10];
    const float* Whh = (const float*)d_in[11];
    const float* bih = (const float*)d_in[12];
    const float* bhh = (const float*)d_in[13];
    const float* W1  = (const float*)d_in[14];
    const float* b1  = (const float*)d_in[15];
    const float* W2  = (const float*)d_in[16];
    const float* b2  = (const float*)d_in[17];
    const float* W3  = (const float*)d_in[18];
    const float* b3  = (const float*)d_in[19];
    float* out = (float*)d_out;

    k_pre<<<B, 512>>>(h0, Wa, ba, Whh, bhh);
    k_scores_mma<<<dim3(T / 128, B, 2), 256>>>(enc, Ua, bua, Va);
    k_ctx<<<B, CTXTH>>>(enc);
    k_dec<<<B, G4>>>(x, c0, Wih, bih, W1, b1, W2, b2, W3, b3, out);
}